// round 1
// baseline (speedup 1.0000x reference)
#include <cuda_runtime.h>

// N=65536 rows, D=512, C=1000. One warp per row.
// Block = 256 threads = 8 warps = 8 rows. Grid = 65536/8 = 8192 blocks.

#define N_ROWS   65536
#define D_DIM    512
#define WARPS_PER_BLOCK 8
#define THREADS  (WARPS_PER_BLOCK * 32)
#define NBLOCKS  (N_ROWS / WARPS_PER_BLOCK)   // 8192

__device__ float g_partial[NBLOCKS];

__global__ __launch_bounds__(THREADS) void center_loss_main(
    const float* __restrict__ x,
    const float* __restrict__ w,
    const int*   __restrict__ t)
{
    const int warp_in_blk = threadIdx.x >> 5;
    const int lane        = threadIdx.x & 31;
    const int row         = blockIdx.x * WARPS_PER_BLOCK + warp_in_blk;

    const float4* xr = reinterpret_cast<const float4*>(x + (size_t)row * D_DIM);
    const int cls = t[row];
    const float4* wr = reinterpret_cast<const float4*>(w + (size_t)cls * D_DIM);

    float acc = 0.0f;
    // 512 floats / 32 lanes = 16 floats = 4 float4 per lane.
    #pragma unroll
    for (int i = 0; i < 4; i++) {
        float4 a = xr[lane + i * 32];
        float4 b = __ldg(&wr[lane + i * 32]);
        float d0 = a.x - b.x;
        float d1 = a.y - b.y;
        float d2 = a.z - b.z;
        float d3 = a.w - b.w;
        acc = fmaf(d0, d0, acc);
        acc = fmaf(d1, d1, acc);
        acc = fmaf(d2, d2, acc);
        acc = fmaf(d3, d3, acc);
    }

    // warp reduce
    #pragma unroll
    for (int o = 16; o > 0; o >>= 1)
        acc += __shfl_xor_sync(0xFFFFFFFFu, acc, o);

    __shared__ float s[WARPS_PER_BLOCK];
    if (lane == 0)
        s[warp_in_blk] = sqrtf(acc + 1e-6f);
    __syncthreads();

    if (threadIdx.x < WARPS_PER_BLOCK) {
        float v = s[threadIdx.x];
        #pragma unroll
        for (int o = WARPS_PER_BLOCK / 2; o > 0; o >>= 1)
            v += __shfl_xor_sync((1u << WARPS_PER_BLOCK) - 1u, v, o);
        if (threadIdx.x == 0)
            g_partial[blockIdx.x] = v;
    }
}

__global__ __launch_bounds__(1024) void center_loss_reduce(float* __restrict__ out)
{
    __shared__ float s[32];
    float v = 0.0f;
    // 8192 partials / 1024 threads = 8 per thread
    #pragma unroll
    for (int i = 0; i < NBLOCKS / 1024; i++)
        v += g_partial[threadIdx.x + i * 1024];

    #pragma unroll
    for (int o = 16; o > 0; o >>= 1)
        v += __shfl_xor_sync(0xFFFFFFFFu, v, o);
    if ((threadIdx.x & 31) == 0)
        s[threadIdx.x >> 5] = v;
    __syncthreads();
    if (threadIdx.x < 32) {
        v = s[threadIdx.x];
        #pragma unroll
        for (int o = 16; o > 0; o >>= 1)
            v += __shfl_xor_sync(0xFFFFFFFFu, v, o);
        if (threadIdx.x == 0)
            out[0] = v * (1.0f / (float)N_ROWS);
    }
}

extern "C" void kernel_launch(void* const* d_in, const int* in_sizes, int n_in,
                              void* d_out, int out_size)
{
    const float* x = (const float*)d_in[0];   // [N, D] fp32
    const float* w = (const float*)d_in[1];   // [C, D] fp32
    const int*   t = (const int*)d_in[2];     // [N] int32
    float* out = (float*)d_out;

    center_loss_main<<<NBLOCKS, THREADS>>>(x, w, t);
    center_loss_reduce<<<1, 1024>>>(out);
}

// round 2
// speedup vs baseline: 1.0590x; 1.0590x over previous
#include <cuda_runtime.h>

// N=65536 rows, D=512, C=1000.
// Grid = 1024 blocks x 512 threads (16 warps). Each warp handles 4 rows
// (interleaved accumulators for MLP/ILP). Fused final reduction via
// last-block-done pattern (deterministic sum order; atomics only on an int
// counter, which the last block resets for graph replay).

#define N_ROWS   65536
#define D_DIM    512
#define GRID     1024
#define THREADS  512
#define WARPS_PER_BLOCK (THREADS / 32)          // 16
#define ROWS_PER_WARP   4                        // 1024*16*4 = 65536

__device__ float g_partial[GRID];
__device__ int   g_count;   // zero-init at load; reset by last block each call

__global__ __launch_bounds__(THREADS) void center_loss_fused(
    const float* __restrict__ x,
    const float* __restrict__ w,
    const int*   __restrict__ t,
    float* __restrict__ out)
{
    const int warp_in_blk = threadIdx.x >> 5;
    const int lane        = threadIdx.x & 31;
    const int gwarp       = blockIdx.x * WARPS_PER_BLOCK + warp_in_blk;
    const int row0        = gwarp * ROWS_PER_WARP;

    float acc[ROWS_PER_WARP];
    #pragma unroll
    for (int r = 0; r < ROWS_PER_WARP; r++) acc[r] = 0.0f;

    const float4* xr[ROWS_PER_WARP];
    const float4* wr[ROWS_PER_WARP];
    #pragma unroll
    for (int r = 0; r < ROWS_PER_WARP; r++) {
        xr[r] = reinterpret_cast<const float4*>(x + (size_t)(row0 + r) * D_DIM);
        wr[r] = reinterpret_cast<const float4*>(w + (size_t)t[row0 + r] * D_DIM);
    }

    // 512 floats / 32 lanes = 4 float4 per lane per row.
    #pragma unroll
    for (int i = 0; i < 4; i++) {
        float4 a[ROWS_PER_WARP], b[ROWS_PER_WARP];
        #pragma unroll
        for (int r = 0; r < ROWS_PER_WARP; r++) a[r] = xr[r][lane + i * 32];
        #pragma unroll
        for (int r = 0; r < ROWS_PER_WARP; r++) b[r] = __ldg(&wr[r][lane + i * 32]);
        #pragma unroll
        for (int r = 0; r < ROWS_PER_WARP; r++) {
            float d0 = a[r].x - b[r].x;
            float d1 = a[r].y - b[r].y;
            float d2 = a[r].z - b[r].z;
            float d3 = a[r].w - b[r].w;
            acc[r] = fmaf(d0, d0, acc[r]);
            acc[r] = fmaf(d1, d1, acc[r]);
            acc[r] = fmaf(d2, d2, acc[r]);
            acc[r] = fmaf(d3, d3, acc[r]);
        }
    }

    // 4 interleaved warp butterfly reductions (ILP hides shfl latency)
    #pragma unroll
    for (int o = 16; o > 0; o >>= 1) {
        #pragma unroll
        for (int r = 0; r < ROWS_PER_WARP; r++)
            acc[r] += __shfl_xor_sync(0xFFFFFFFFu, acc[r], o);
    }

    __shared__ float s[WARPS_PER_BLOCK];
    if (lane == 0) {
        float v = 0.0f;
        #pragma unroll
        for (int r = 0; r < ROWS_PER_WARP; r++)
            v += sqrtf(acc[r] + 1e-6f);
        s[warp_in_blk] = v;
    }
    __syncthreads();

    __shared__ bool is_last;
    if (threadIdx.x == 0) {
        float v = 0.0f;
        #pragma unroll
        for (int i = 0; i < WARPS_PER_BLOCK; i++) v += s[i];
        g_partial[blockIdx.x] = v;
        __threadfence();
        int old = atomicAdd(&g_count, 1);
        is_last = (old == GRID - 1);
    }
    __syncthreads();

    if (is_last) {
        // Deterministic final reduce over 1024 partials with 512 threads.
        float v = g_partial[threadIdx.x] + g_partial[threadIdx.x + THREADS];
        #pragma unroll
        for (int o = 16; o > 0; o >>= 1)
            v += __shfl_xor_sync(0xFFFFFFFFu, v, o);
        __shared__ float fs[WARPS_PER_BLOCK];
        if (lane == 0) fs[warp_in_blk] = v;
        __syncthreads();
        if (threadIdx.x < 32) {
            float u = (lane < WARPS_PER_BLOCK) ? fs[lane] : 0.0f;
            #pragma unroll
            for (int o = 16; o > 0; o >>= 1)
                u += __shfl_xor_sync(0xFFFFFFFFu, u, o);
            if (threadIdx.x == 0) {
                out[0] = u * (1.0f / (float)N_ROWS);
                g_count = 0;   // reset for next graph replay
            }
        }
    }
}

extern "C" void kernel_launch(void* const* d_in, const int* in_sizes, int n_in,
                              void* d_out, int out_size)
{
    const float* x = (const float*)d_in[0];   // [N, D] fp32
    const float* w = (const float*)d_in[1];   // [C, D] fp32
    const int*   t = (const int*)d_in[2];     // [N] int32
    float* out = (float*)d_out;

    center_loss_fused<<<GRID, THREADS>>>(x, w, t, out);
}